// round 7
// baseline (speedup 1.0000x reference)
#include <cuda_runtime.h>
#include <cuda_bf16.h>
#include <math.h>

#define N_ROWS 8192
#define D_DIM  128
#define CGX 8
#define CGY 64
#define CROSS_BLOCKS (CGX * CGY)
#define PB 24              // smem pitch in bf16 (48B): conflict-free frag loads

// ---------------- device scratch ----------------
__device__ float         d_F[2][N_ROWS * D_DIM];   // compacted features (recheck)
__device__ __nv_bfloat16 d_Ebf[2][N_ROWS * 16];    // bf16 screen rows, 16 dims
__device__ float         d_rsq[2][N_ROWS];
__device__ int           d_cnt[2];
__device__ float         d_vsum[2][D_DIM];
__device__ double        d_acc[4];                 // focal, graph, Snorm0, Snorm1
__device__ double        d_cross;
__device__ unsigned      d_done;

__device__ __forceinline__ float warp_sum(float v) {
    #pragma unroll
    for (int o = 16; o > 0; o >>= 1) v += __shfl_xor_sync(0xffffffffu, v, o);
    return v;
}

// ---------------- partition + focal + graph + class stats ----------------
__global__ void __launch_bounds__(256) partition_kernel(
    const float* __restrict__ preds,
    const float* __restrict__ targets,
    const float* __restrict__ features,
    const float* __restrict__ gfeat)
{
    __shared__ float s_v[8][D_DIM];
    __shared__ float s_sn[2];
    __shared__ float s_focal, s_graph;
    __shared__ int   s_lab[8];
    __shared__ int   s_base[2];

    int tid = threadIdx.x;
    if (tid == 254) { s_sn[0] = 0.0f; s_sn[1] = 0.0f; }
    if (tid == 255) { s_focal = 0.0f; s_graph = 0.0f; }

    int warp = tid >> 5, lane = tid & 31;
    int i = blockIdx.x * 8 + warp;

    float4 f = *(const float4*)(features + (size_t)i * D_DIM + lane * 4);
    float c  = f.x*f.x + f.y*f.y + f.z*f.z + f.w*f.w;
    float nsq  = warp_sum(c);
    float nsq8 = warp_sum(lane < 2 ? c : 0.0f);

    float tgt = targets[i];
    int lab = (tgt > 0.5f) ? 1 : 0;
    if (lane == 0) s_lab[warp] = lab;

    s_v[warp][lane * 4 + 0] = f.x;
    s_v[warp][lane * 4 + 1] = f.y;
    s_v[warp][lane * 4 + 2] = f.z;
    s_v[warp][lane * 4 + 3] = f.w;
    __syncthreads();

    if (tid == 0) {
        int c1 = 0;
        #pragma unroll
        for (int w = 0; w < 8; ++w) c1 += s_lab[w];
        s_base[0] = atomicAdd(&d_cnt[0], 8 - c1);
        s_base[1] = atomicAdd(&d_cnt[1], c1);
    }
    __syncthreads();

    int rank = 0;
    #pragma unroll
    for (int w = 0; w < 8; ++w) rank += (w < warp && s_lab[w] == lab);
    int idx = s_base[lab] + rank;

    *(float4*)(d_F[lab] + (size_t)idx * D_DIM + lane * 4) = f;
    if (lane == 0) d_rsq[lab][idx] = nsq;

    {   // bf16 screen row: dims0-7 = +/-sqrt2*x, dims8-9 aux, 10-15 zero
        float s = (lab == 0) ? -1.41421356237f : 1.41421356237f;
        __nv_bfloat16* E = d_Ebf[lab] + (size_t)idx * 16;
        if (lane < 2) {
            __nv_bfloat162 p0 = __floats2bfloat162_rn(s*f.x, s*f.y);
            __nv_bfloat162 p1 = __floats2bfloat162_rn(s*f.z, s*f.w);
            *(__nv_bfloat162*)(E + lane * 4)     = p0;
            *(__nv_bfloat162*)(E + lane * 4 + 2) = p1;
        }
        if (lane == 2) {
            __nv_bfloat16 nb  = __float2bfloat16(nsq8);
            __nv_bfloat16 one = __float2bfloat16(1.0f);
            __nv_bfloat162 aux = (lab == 0) ? __halves2bfloat162(nb, one)
                                            : __halves2bfloat162(one, nb);
            uint4 v;
            v.x = *reinterpret_cast<unsigned*>(&aux);
            v.y = 0u; v.z = 0u; v.w = 0u;
            *(uint4*)(E + 8) = v;
        }
    }

    if (lane == 0) atomicAdd(&s_sn[lab], nsq);
    if (lane == 0) {
        float p = preds[i];
        float bce = fmaxf(p, 0.0f) - p * tgt + log1pf(expf(-fabsf(p)));
        float pt = expf(-bce);
        float om = 1.0f - pt;
        atomicAdd(&s_focal, 0.25f * om * om * bce);
    }

    if (i >= 1) {
        const float4 a = *(const float4*)(gfeat + (size_t)i       * D_DIM + lane * 4);
        const float4 b = *(const float4*)(gfeat + (size_t)(i - 1) * D_DIM + lane * 4);
        float dx = a.x - b.x, dy = a.y - b.y, dz = a.z - b.z, dw = a.w - b.w;
        float ds = warp_sum(dx*dx + dy*dy + dz*dz + dw*dw);
        if (lane == 0) atomicAdd(&s_graph, sqrtf(ds));
    }
    __syncthreads();

    {
        int cls = tid >> 7, comp = tid & 127;
        float sum = 0.0f;
        #pragma unroll
        for (int w = 0; w < 8; ++w)
            if (s_lab[w] == cls) sum += s_v[w][comp];
        if (sum != 0.0f) atomicAdd(&d_vsum[cls][comp], sum);
    }
    if (tid == 0) {
        atomicAdd(&d_acc[0], (double)s_focal);
        atomicAdd(&d_acc[1], (double)s_graph);
        atomicAdd(&d_acc[2], (double)s_sn[0]);
        atomicAdd(&d_acc[3], (double)s_sn[1]);
    }
}

// exact fp32 recheck; out-of-line, never touches mma regs
__device__ __noinline__ float rare_pair(int gi, int gj) {
    const float* A = d_F[0] + (size_t)gi * D_DIM;
    const float* B = d_F[1] + (size_t)gj * D_DIM;
    float dot = 0.0f;
    #pragma unroll 4
    for (int d = 0; d < D_DIM; ++d) dot += A[d] * B[d];
    float sq = fmaxf(d_rsq[0][gi] + d_rsq[1][gj] - 2.0f * dot, 0.0f);
    float t = 1.0f - sqrtf(sq);
    return (t > 0.0f) ? t * t : 0.0f;
}

// ---------------- cross-label screen via bf16 HMMA (acc == sq8) -------------
__global__ void __launch_bounds__(256) cross_kernel(float* __restrict__ out) {
    __shared__ __nv_bfloat16 sA[128 * PB];
    __shared__ __nv_bfloat16 sB[128 * PB];
    __shared__ float redw[8];
    __shared__ unsigned s_ticket;

    int n0 = d_cnt[0], n1 = d_cnt[1];
    int tiles_r = (n0 + 127) >> 7;
    int tiles_c = (n1 + 127) >> 7;
    int tid = threadIdx.x;
    int tr = blockIdx.y;

    float lsum = 0.0f;

    if (tr < tiles_r) {
        int row0 = tr * 128;
        int wid = tid >> 5, lane = tid & 31;
        int g = lane >> 2, t = lane & 3;
        int r0 = (wid & 3) * 32;        // warp row base within tile
        int c0 = (wid >> 2) * 64;       // warp col base within tile

        int ldr = tid >> 1, ldh = tid & 1;   // loader: row, 16B half
        const uint4 pad = make_uint4(0u, 0u, 0u, 0u);
        const uint4 padaux = make_uint4(0x71157115u, 0u, 0u, 0u);  // BIG,BIG,...

        // ---- A tile (128 x 16 bf16, pitch PB) ----
        {
            uint4 v = ldh ? padaux : pad;
            if (row0 + ldr < n0)
                v = *((const uint4*)(d_Ebf[0] + (size_t)(row0 + ldr) * 16) + ldh);
            *(uint4*)(sA + ldr * PB + ldh * 8) = v;
        }

        for (int tc = blockIdx.x; tc < tiles_c; tc += CGX) {
            int col0 = tc * 128;
            __syncthreads();    // prior compute done (and A visible on 1st iter)
            {
                uint4 v = ldh ? padaux : pad;
                if (col0 + ldr < n1)
                    v = *((const uint4*)(d_Ebf[1] + (size_t)(col0 + ldr) * 16) + ldh);
                *(uint4*)(sB + ldr * PB + ldh * 8) = v;
            }
            __syncthreads();

            // ---- A fragments (reused across 8 col blocks) ----
            unsigned a[2][4];
            #pragma unroll
            for (int rb = 0; rb < 2; ++rb) {
                const __nv_bfloat16* base = sA + (r0 + rb * 16 + g) * PB + t * 2;
                a[rb][0] = *(const unsigned*)(base);
                a[rb][1] = *(const unsigned*)(base + 8 * PB);
                a[rb][2] = *(const unsigned*)(base + 8);
                a[rb][3] = *(const unsigned*)(base + 8 * PB + 8);
            }

            float m = 1e30f;
            #pragma unroll
            for (int cb = 0; cb < 8; ++cb) {
                const __nv_bfloat16* bb = sB + (c0 + cb * 8 + g) * PB + t * 2;
                unsigned b0 = *(const unsigned*)(bb);
                unsigned b1 = *(const unsigned*)(bb + 8);
                #pragma unroll
                for (int rb = 0; rb < 2; ++rb) {
                    float d0, d1, d2, d3;
                    asm("mma.sync.aligned.m16n8k16.row.col.f32.bf16.bf16.f32 "
                        "{%0,%1,%2,%3},{%4,%5,%6,%7},{%8,%9},{%10,%10,%10,%10};"
                        : "=f"(d0), "=f"(d1), "=f"(d2), "=f"(d3)
                        : "r"(a[rb][0]), "r"(a[rb][1]), "r"(a[rb][2]), "r"(a[rb][3]),
                          "r"(b0), "r"(b1), "f"(0.0f));
                    m = fminf(m, fminf(fminf(d0, d1), fminf(d2, d3)));
                }
            }

            if (m < 1.5f) {   // rare: rescan this thread's 64 pairs exactly
                #pragma unroll 1
                for (int rb = 0; rb < 2; ++rb) {
                    #pragma unroll 1
                    for (int cb = 0; cb < 8; ++cb) {
                        #pragma unroll 1
                        for (int q = 0; q < 4; ++q) {
                            int gi = row0 + r0 + rb * 16 + g + (q >> 1) * 8;
                            int gj = col0 + c0 + cb * 8 + t * 2 + (q & 1);
                            if (gi < n0 && gj < n1) lsum += rare_pair(gi, gj);
                        }
                    }
                }
            }
        }
    }

    // ---- one reduction per block ----
    lsum = warp_sum(lsum);
    if ((tid & 31) == 0) redw[tid >> 5] = lsum;
    __syncthreads();
    if (tid == 0) {
        float s = 0.0f;
        #pragma unroll
        for (int w = 0; w < 8; ++w) s += redw[w];
        if (s != 0.0f) atomicAdd(&d_cross, (double)s);
    }

    // ---- completion ticket: last block finalizes + resets ----
    __threadfence();
    if (tid == 0) s_ticket = atomicAdd(&d_done, 1u);
    __syncthreads();
    if (s_ticket == CROSS_BLOCKS - 1) {
        __threadfence();
        __shared__ double s[256];
        int cls = tid >> 7, comp = tid & 127;
        double v = (double)d_vsum[cls][comp];
        s[tid] = v * v;
        __syncthreads();
        for (int st = 64; st > 0; st >>= 1) {
            if (comp < st) s[tid] += s[tid + st];
            __syncthreads();
        }
        if (tid == 0) {
            double vn0 = s[0], vn1 = s[128];
            double dn0 = (double)n0, dn1 = (double)n1;
            double same = 2.0 * (dn0 * d_acc[2] - vn0) + 2.0 * (dn1 * d_acc[3] - vn1);
            double NN = (double)N_ROWS * (double)N_ROWS;
            double contrast = (same + 2.0 * d_cross) / NN;
            double focal = d_acc[0] / (double)N_ROWS;
            double graph = 0.1 * d_acc[1] / (double)(N_ROWS - 1);
            out[0] = (float)(focal + contrast + graph);
            d_cnt[0] = 0; d_cnt[1] = 0;
            d_acc[0] = 0.0; d_acc[1] = 0.0; d_acc[2] = 0.0; d_acc[3] = 0.0;
            d_cross = 0.0;
            d_done = 0u;
        }
        d_vsum[cls][comp] = 0.0f;
    }
}

// ---------------- launch ----------------
extern "C" void kernel_launch(void* const* d_in, const int* in_sizes, int n_in,
                              void* d_out, int out_size) {
    const float* preds    = (const float*)d_in[0];
    const float* targets  = (const float*)d_in[1];
    const float* features = (const float*)d_in[2];
    const float* gfeat    = (const float*)d_in[3];
    float* out = (float*)d_out;

    partition_kernel<<<N_ROWS / 8, 256>>>(preds, targets, features, gfeat);
    cross_kernel<<<dim3(CGX, CGY), 256>>>(out);
}

// round 8
// speedup vs baseline: 8.5527x; 8.5527x over previous
#include <cuda_runtime.h>
#include <cuda_bf16.h>
#include <math.h>

#define N_ROWS 8192
#define D_DIM  128
#define CGX 8
#define CGY 64
#define CROSS_BLOCKS (CGX * CGY)
#define PB 24              // smem pitch in bf16 (48B): conflict-free frag loads

// ---------------- device scratch ----------------
__device__ float         d_F[2][N_ROWS * D_DIM];   // compacted features (recheck)
__device__ __nv_bfloat16 d_Ebf[2][N_ROWS * 16];    // bf16 screen rows, 16 dims
__device__ float         d_rsq[2][N_ROWS];
__device__ unsigned long long d_cnt64;             // packed counts: lo=class0, hi=class1
__device__ float         d_vsum[2][D_DIM];
__device__ double        d_acc[4];                 // focal, graph, Snorm0, Snorm1
__device__ double        d_cross;
__device__ unsigned      d_done;

__device__ __forceinline__ float warp_sum(float v) {
    #pragma unroll
    for (int o = 16; o > 0; o >>= 1) v += __shfl_xor_sync(0xffffffffu, v, o);
    return v;
}

// ---------------- partition + focal + graph + class stats ----------------
__global__ void __launch_bounds__(256) partition_kernel(
    const float* __restrict__ preds,
    const float* __restrict__ targets,
    const float* __restrict__ features,
    const float* __restrict__ gfeat)
{
    __shared__ float s_v[8][D_DIM];
    __shared__ float s_sn[2];
    __shared__ float s_focal, s_graph;
    __shared__ int   s_lab[8];
    __shared__ int   s_base[2];

    int tid = threadIdx.x;
    if (tid == 254) { s_sn[0] = 0.0f; s_sn[1] = 0.0f; }
    if (tid == 255) { s_focal = 0.0f; s_graph = 0.0f; }

    int warp = tid >> 5, lane = tid & 31;
    int i = blockIdx.x * 8 + warp;

    float4 f = *(const float4*)(features + (size_t)i * D_DIM + lane * 4);
    float c  = f.x*f.x + f.y*f.y + f.z*f.z + f.w*f.w;
    float nsq  = warp_sum(c);
    float nsq8 = warp_sum(lane < 2 ? c : 0.0f);

    float tgt = targets[i];
    int lab = (tgt > 0.5f) ? 1 : 0;
    if (lane == 0) s_lab[warp] = lab;

    s_v[warp][lane * 4 + 0] = f.x;
    s_v[warp][lane * 4 + 1] = f.y;
    s_v[warp][lane * 4 + 2] = f.z;
    s_v[warp][lane * 4 + 3] = f.w;
    __syncthreads();

    if (tid == 0) {
        int c1 = 0;
        #pragma unroll
        for (int w = 0; w < 8; ++w) c1 += s_lab[w];
        unsigned long long add = ((unsigned long long)c1 << 32)
                               | (unsigned long long)(8 - c1);
        unsigned long long old = atomicAdd(&d_cnt64, add);
        s_base[0] = (int)(old & 0xffffffffull);
        s_base[1] = (int)(old >> 32);
    }
    __syncthreads();

    int rank = 0;
    #pragma unroll
    for (int w = 0; w < 8; ++w) rank += (w < warp && s_lab[w] == lab);
    int idx = s_base[lab] + rank;

    *(float4*)(d_F[lab] + (size_t)idx * D_DIM + lane * 4) = f;
    if (lane == 0) d_rsq[lab][idx] = nsq;

    {   // bf16 screen row: dims0-7 = +/-sqrt2*x, dims8-9 aux, 10-15 zero
        float s = (lab == 0) ? -1.41421356237f : 1.41421356237f;
        __nv_bfloat16* E = d_Ebf[lab] + (size_t)idx * 16;
        if (lane < 2) {
            __nv_bfloat162 p0 = __floats2bfloat162_rn(s*f.x, s*f.y);
            __nv_bfloat162 p1 = __floats2bfloat162_rn(s*f.z, s*f.w);
            *(__nv_bfloat162*)(E + lane * 4)     = p0;
            *(__nv_bfloat162*)(E + lane * 4 + 2) = p1;
        }
        if (lane == 2) {
            __nv_bfloat16 nb  = __float2bfloat16(nsq8);
            __nv_bfloat16 one = __float2bfloat16(1.0f);
            __nv_bfloat162 aux = (lab == 0) ? __halves2bfloat162(nb, one)
                                            : __halves2bfloat162(one, nb);
            uint4 v;
            v.x = *reinterpret_cast<unsigned*>(&aux);
            v.y = 0u; v.z = 0u; v.w = 0u;
            *(uint4*)(E + 8) = v;
        }
    }

    if (lane == 0) atomicAdd(&s_sn[lab], nsq);
    if (lane == 0) {
        float p = preds[i];
        float bce = fmaxf(p, 0.0f) - p * tgt + log1pf(expf(-fabsf(p)));
        float pt = expf(-bce);
        float om = 1.0f - pt;
        atomicAdd(&s_focal, 0.25f * om * om * bce);
    }

    if (i >= 1) {
        const float4 a = *(const float4*)(gfeat + (size_t)i       * D_DIM + lane * 4);
        const float4 b = *(const float4*)(gfeat + (size_t)(i - 1) * D_DIM + lane * 4);
        float dx = a.x - b.x, dy = a.y - b.y, dz = a.z - b.z, dw = a.w - b.w;
        float ds = warp_sum(dx*dx + dy*dy + dz*dz + dw*dw);
        if (lane == 0) atomicAdd(&s_graph, sqrtf(ds));
    }
    __syncthreads();

    {
        int cls = tid >> 7, comp = tid & 127;
        float sum = 0.0f;
        #pragma unroll
        for (int w = 0; w < 8; ++w)
            if (s_lab[w] == cls) sum += s_v[w][comp];
        if (sum != 0.0f) atomicAdd(&d_vsum[cls][comp], sum);
    }
    if (tid == 0) {
        atomicAdd(&d_acc[0], (double)s_focal);
        atomicAdd(&d_acc[1], (double)s_graph);
        atomicAdd(&d_acc[2], (double)s_sn[0]);
        atomicAdd(&d_acc[3], (double)s_sn[1]);
    }
}

// exact fp32 recheck; out-of-line, never touches mma regs
__device__ __noinline__ float rare_pair(int gi, int gj) {
    const float* A = d_F[0] + (size_t)gi * D_DIM;
    const float* B = d_F[1] + (size_t)gj * D_DIM;
    float dot = 0.0f;
    #pragma unroll 4
    for (int d = 0; d < D_DIM; ++d) dot += A[d] * B[d];
    float sq = fmaxf(d_rsq[0][gi] + d_rsq[1][gj] - 2.0f * dot, 0.0f);
    float t = 1.0f - sqrtf(sq);
    return (t > 0.0f) ? t * t : 0.0f;
}

// ---------------- cross-label screen via bf16 HMMA (acc == sq8) -------------
__global__ void __launch_bounds__(256) cross_kernel(float* __restrict__ out) {
    __shared__ __nv_bfloat16 sA[128 * PB];
    __shared__ __nv_bfloat16 sB[128 * PB];
    __shared__ float redw[8];
    __shared__ unsigned s_ticket;

    unsigned long long cnt = d_cnt64;
    int n0 = (int)(cnt & 0xffffffffull);
    int n1 = (int)(cnt >> 32);
    int tiles_r = (n0 + 127) >> 7;
    int tiles_c = (n1 + 127) >> 7;
    int tid = threadIdx.x;
    int tr = blockIdx.y;

    float lsum = 0.0f;

    if (tr < tiles_r) {
        int row0 = tr * 128;
        int wid = tid >> 5, lane = tid & 31;
        int g = lane >> 2, t = lane & 3;
        int r0 = (wid & 3) * 32;        // warp row base within tile
        int c0 = (wid >> 2) * 64;       // warp col base within tile

        int ldr = tid >> 1, ldh = tid & 1;
        const uint4 pad = make_uint4(0u, 0u, 0u, 0u);
        const uint4 padaux = make_uint4(0x71157115u, 0u, 0u, 0u);  // BIG,BIG

        // ---- A tile (128 x 16 bf16, pitch PB) ----
        {
            uint4 v = ldh ? padaux : pad;
            if (row0 + ldr < n0)
                v = *((const uint4*)(d_Ebf[0] + (size_t)(row0 + ldr) * 16) + ldh);
            *(uint4*)(sA + ldr * PB + ldh * 8) = v;
        }

        for (int tc = blockIdx.x; tc < tiles_c; tc += CGX) {
            int col0 = tc * 128;
            __syncthreads();
            {
                uint4 v = ldh ? padaux : pad;
                if (col0 + ldr < n1)
                    v = *((const uint4*)(d_Ebf[1] + (size_t)(col0 + ldr) * 16) + ldh);
                *(uint4*)(sB + ldr * PB + ldh * 8) = v;
            }
            __syncthreads();

            // ---- A fragments (reused across 8 col blocks) ----
            unsigned a[2][4];
            #pragma unroll
            for (int rb = 0; rb < 2; ++rb) {
                const __nv_bfloat16* base = sA + (r0 + rb * 16 + g) * PB + t * 2;
                a[rb][0] = *(const unsigned*)(base);
                a[rb][1] = *(const unsigned*)(base + 8 * PB);
                a[rb][2] = *(const unsigned*)(base + 8);
                a[rb][3] = *(const unsigned*)(base + 8 * PB + 8);
            }

            // 16-bit fragment mask: bit (cb*2+rb) set if that 16x8 frag
            // has any value < 1.5 for this thread's 4 outputs
            unsigned fmask = 0u;
            #pragma unroll
            for (int cb = 0; cb < 8; ++cb) {
                const __nv_bfloat16* bb = sB + (c0 + cb * 8 + g) * PB + t * 2;
                unsigned b0 = *(const unsigned*)(bb);
                unsigned b1 = *(const unsigned*)(bb + 8);
                #pragma unroll
                for (int rb = 0; rb < 2; ++rb) {
                    float d0, d1, d2, d3;
                    asm("mma.sync.aligned.m16n8k16.row.col.f32.bf16.bf16.f32 "
                        "{%0,%1,%2,%3},{%4,%5,%6,%7},{%8,%9},{%10,%10,%10,%10};"
                        : "=f"(d0), "=f"(d1), "=f"(d2), "=f"(d3)
                        : "r"(a[rb][0]), "r"(a[rb][1]), "r"(a[rb][2]), "r"(a[rb][3]),
                          "r"(b0), "r"(b1), "f"(0.0f));
                    float mn = fminf(fminf(d0, d1), fminf(d2, d3));
                    if (mn < 1.5f) fmask |= 1u << (cb * 2 + rb);
                }
            }

            if (fmask) {   // rare: rescan only flagged 4-pair quads
                #pragma unroll 1
                while (fmask) {
                    int b = __ffs(fmask) - 1;
                    fmask &= fmask - 1;
                    int cb = b >> 1, rb = b & 1;
                    int gib = row0 + r0 + rb * 16 + g;
                    int gjb = col0 + c0 + cb * 8 + t * 2;
                    #pragma unroll 1
                    for (int q = 0; q < 4; ++q) {
                        int gi = gib + (q >> 1) * 8;
                        int gj = gjb + (q & 1);
                        if (gi < n0 && gj < n1) lsum += rare_pair(gi, gj);
                    }
                }
            }
        }
    }

    // ---- one reduction per block ----
    lsum = warp_sum(lsum);
    if ((tid & 31) == 0) redw[tid >> 5] = lsum;
    __syncthreads();
    if (tid == 0) {
        float s = 0.0f;
        #pragma unroll
        for (int w = 0; w < 8; ++w) s += redw[w];
        if (s != 0.0f) atomicAdd(&d_cross, (double)s);
    }

    // ---- completion ticket: last block finalizes + resets ----
    __threadfence();
    if (tid == 0) s_ticket = atomicAdd(&d_done, 1u);
    __syncthreads();
    if (s_ticket == CROSS_BLOCKS - 1) {
        __threadfence();
        __shared__ double s[256];
        int cls = tid >> 7, comp = tid & 127;
        double v = (double)d_vsum[cls][comp];
        s[tid] = v * v;
        __syncthreads();
        for (int st = 64; st > 0; st >>= 1) {
            if (comp < st) s[tid] += s[tid + st];
            __syncthreads();
        }
        if (tid == 0) {
            double vn0 = s[0], vn1 = s[128];
            double dn0 = (double)n0, dn1 = (double)n1;
            double same = 2.0 * (dn0 * d_acc[2] - vn0) + 2.0 * (dn1 * d_acc[3] - vn1);
            double NN = (double)N_ROWS * (double)N_ROWS;
            double contrast = (same + 2.0 * d_cross) / NN;
            double focal = d_acc[0] / (double)N_ROWS;
            double graph = 0.1 * d_acc[1] / (double)(N_ROWS - 1);
            out[0] = (float)(focal + contrast + graph);
            d_cnt64 = 0ull;
            d_acc[0] = 0.0; d_acc[1] = 0.0; d_acc[2] = 0.0; d_acc[3] = 0.0;
            d_cross = 0.0;
            d_done = 0u;
        }
        d_vsum[cls][comp] = 0.0f;
    }
}

// ---------------- launch ----------------
extern "C" void kernel_launch(void* const* d_in, const int* in_sizes, int n_in,
                              void* d_out, int out_size) {
    const float* preds    = (const float*)d_in[0];
    const float* targets  = (const float*)d_in[1];
    const float* features = (const float*)d_in[2];
    const float* gfeat    = (const float*)d_in[3];
    float* out = (float*)d_out;

    partition_kernel<<<N_ROWS / 8, 256>>>(preds, targets, features, gfeat);
    cross_kernel<<<dim3(CGX, CGY), 256>>>(out);
}

// round 9
// speedup vs baseline: 31.4463x; 3.6768x over previous
#include <cuda_runtime.h>
#include <cuda_bf16.h>
#include <math.h>

#define N_ROWS 8192
#define D_DIM  128
#define CGX 8
#define CGY 64
#define CROSS_BLOCKS (CGX * CGY)
#define PB 24              // smem pitch in bf16 (48B): conflict-free frag loads

// ---------------- device scratch ----------------
__device__ float         d_F[2][N_ROWS * D_DIM];   // compacted features (recheck)
__device__ __nv_bfloat16 d_Ebf[2][N_ROWS * 16];    // bf16 screen rows: 14 dims + 2 aux
__device__ float         d_rsq[2][N_ROWS];
__device__ unsigned long long d_cnt64;             // packed counts: lo=class0, hi=class1
__device__ float         d_vsum[2][D_DIM];
__device__ double        d_acc[4];                 // focal, graph, Snorm0, Snorm1
__device__ double        d_cross;
__device__ unsigned      d_done;

__device__ __forceinline__ float warp_sum(float v) {
    #pragma unroll
    for (int o = 16; o > 0; o >>= 1) v += __shfl_xor_sync(0xffffffffu, v, o);
    return v;
}

// ---------------- partition + focal + graph + class stats ----------------
__global__ void __launch_bounds__(256) partition_kernel(
    const float* __restrict__ preds,
    const float* __restrict__ targets,
    const float* __restrict__ features,
    const float* __restrict__ gfeat)
{
    __shared__ float s_v[8][D_DIM];
    __shared__ float s_sn[2];
    __shared__ float s_focal, s_graph;
    __shared__ int   s_lab[8];
    __shared__ int   s_base[2];

    int tid = threadIdx.x;
    if (tid == 254) { s_sn[0] = 0.0f; s_sn[1] = 0.0f; }
    if (tid == 255) { s_focal = 0.0f; s_graph = 0.0f; }

    int warp = tid >> 5, lane = tid & 31;
    int i = blockIdx.x * 8 + warp;

    float4 f = *(const float4*)(features + (size_t)i * D_DIM + lane * 4);
    float c  = f.x*f.x + f.y*f.y + f.z*f.z + f.w*f.w;
    float nsq   = warp_sum(c);
    // dims [0,14): lanes 0-2 full, lane 3 contributes dims 12,13 only
    float c14 = (lane < 3) ? c : ((lane == 3) ? (f.x*f.x + f.y*f.y) : 0.0f);
    float nsq14 = warp_sum(c14);

    float tgt = targets[i];
    int lab = (tgt > 0.5f) ? 1 : 0;
    if (lane == 0) s_lab[warp] = lab;

    s_v[warp][lane * 4 + 0] = f.x;
    s_v[warp][lane * 4 + 1] = f.y;
    s_v[warp][lane * 4 + 2] = f.z;
    s_v[warp][lane * 4 + 3] = f.w;
    __syncthreads();

    if (tid == 0) {
        int c1 = 0;
        #pragma unroll
        for (int w = 0; w < 8; ++w) c1 += s_lab[w];
        unsigned long long add = ((unsigned long long)c1 << 32)
                               | (unsigned long long)(8 - c1);
        unsigned long long old = atomicAdd(&d_cnt64, add);
        s_base[0] = (int)(old & 0xffffffffull);
        s_base[1] = (int)(old >> 32);
    }
    __syncthreads();

    int rank = 0;
    #pragma unroll
    for (int w = 0; w < 8; ++w) rank += (w < warp && s_lab[w] == lab);
    int idx = s_base[lab] + rank;

    *(float4*)(d_F[lab] + (size_t)idx * D_DIM + lane * 4) = f;
    if (lane == 0) d_rsq[lab][idx] = nsq;

    {   // bf16 screen row: dims0-13 = +/-sqrt2*x, dims14-15 aux
        float s = (lab == 0) ? -1.41421356237f : 1.41421356237f;
        __nv_bfloat16* E = d_Ebf[lab] + (size_t)idx * 16;
        if (lane < 3) {
            __nv_bfloat162 p0 = __floats2bfloat162_rn(s*f.x, s*f.y);
            __nv_bfloat162 p1 = __floats2bfloat162_rn(s*f.z, s*f.w);
            *(__nv_bfloat162*)(E + lane * 4)     = p0;
            *(__nv_bfloat162*)(E + lane * 4 + 2) = p1;
        } else if (lane == 3) {
            __nv_bfloat162 p0 = __floats2bfloat162_rn(s*f.x, s*f.y);  // dims 12,13
            __nv_bfloat16 nb  = __float2bfloat16(nsq14);
            __nv_bfloat16 one = __float2bfloat16(1.0f);
            __nv_bfloat162 aux = (lab == 0) ? __halves2bfloat162(nb, one)
                                            : __halves2bfloat162(one, nb);
            *(__nv_bfloat162*)(E + 12) = p0;
            *(__nv_bfloat162*)(E + 14) = aux;
        }
    }

    if (lane == 0) atomicAdd(&s_sn[lab], nsq);
    if (lane == 0) {
        float p = preds[i];
        float bce = fmaxf(p, 0.0f) - p * tgt + log1pf(expf(-fabsf(p)));
        float pt = expf(-bce);
        float om = 1.0f - pt;
        atomicAdd(&s_focal, 0.25f * om * om * bce);
    }

    if (i >= 1) {
        const float4 a = *(const float4*)(gfeat + (size_t)i       * D_DIM + lane * 4);
        const float4 b = *(const float4*)(gfeat + (size_t)(i - 1) * D_DIM + lane * 4);
        float dx = a.x - b.x, dy = a.y - b.y, dz = a.z - b.z, dw = a.w - b.w;
        float ds = warp_sum(dx*dx + dy*dy + dz*dz + dw*dw);
        if (lane == 0) atomicAdd(&s_graph, sqrtf(ds));
    }
    __syncthreads();

    {
        int cls = tid >> 7, comp = tid & 127;
        float sum = 0.0f;
        #pragma unroll
        for (int w = 0; w < 8; ++w)
            if (s_lab[w] == cls) sum += s_v[w][comp];
        if (sum != 0.0f) atomicAdd(&d_vsum[cls][comp], sum);
    }
    if (tid == 0) {
        atomicAdd(&d_acc[0], (double)s_focal);
        atomicAdd(&d_acc[1], (double)s_graph);
        atomicAdd(&d_acc[2], (double)s_sn[0]);
        atomicAdd(&d_acc[3], (double)s_sn[1]);
    }
}

// exact fp32 recheck; out-of-line, never touches mma regs
__device__ __noinline__ float rare_pair(int gi, int gj) {
    const float* A = d_F[0] + (size_t)gi * D_DIM;
    const float* B = d_F[1] + (size_t)gj * D_DIM;
    float dot = 0.0f;
    #pragma unroll 4
    for (int d = 0; d < D_DIM; ++d) dot += A[d] * B[d];
    float sq = fmaxf(d_rsq[0][gi] + d_rsq[1][gj] - 2.0f * dot, 0.0f);
    float t = 1.0f - sqrtf(sq);
    return (t > 0.0f) ? t * t : 0.0f;
}

// ---------------- cross-label screen via bf16 HMMA (acc == sq14) ------------
__global__ void __launch_bounds__(256) cross_kernel(float* __restrict__ out) {
    __shared__ __nv_bfloat16 sA[128 * PB];
    __shared__ __nv_bfloat16 sB[128 * PB];
    __shared__ float redw[8];
    __shared__ unsigned s_ticket;

    unsigned long long cnt = d_cnt64;
    int n0 = (int)(cnt & 0xffffffffull);
    int n1 = (int)(cnt >> 32);
    int tiles_r = (n0 + 127) >> 7;
    int tiles_c = (n1 + 127) >> 7;
    int tid = threadIdx.x;
    int tr = blockIdx.y;

    float lsum = 0.0f;

    if (tr < tiles_r) {
        int row0 = tr * 128;
        int wid = tid >> 5, lane = tid & 31;
        int g = lane >> 2, t = lane & 3;
        int r0 = (wid & 3) * 32;        // warp row base within tile
        int c0 = (wid >> 2) * 64;       // warp col base within tile

        int ldr = tid >> 1, ldh = tid & 1;
        const uint4 pad = make_uint4(0u, 0u, 0u, 0u);
        // padding rows: dims 8-13 = 0, dims 14,15 = BIG (aux product blows up)
        const uint4 padaux = make_uint4(0u, 0u, 0u, 0x71157115u);

        // ---- A tile (128 x 16 bf16, pitch PB) ----
        {
            uint4 v = ldh ? padaux : pad;
            if (row0 + ldr < n0)
                v = *((const uint4*)(d_Ebf[0] + (size_t)(row0 + ldr) * 16) + ldh);
            *(uint4*)(sA + ldr * PB + ldh * 8) = v;
        }

        for (int tc = blockIdx.x; tc < tiles_c; tc += CGX) {
            int col0 = tc * 128;
            __syncthreads();
            {
                uint4 v = ldh ? padaux : pad;
                if (col0 + ldr < n1)
                    v = *((const uint4*)(d_Ebf[1] + (size_t)(col0 + ldr) * 16) + ldh);
                *(uint4*)(sB + ldr * PB + ldh * 8) = v;
            }
            __syncthreads();

            // ---- A fragments (reused across 8 col blocks) ----
            unsigned a[2][4];
            #pragma unroll
            for (int rb = 0; rb < 2; ++rb) {
                const __nv_bfloat16* base = sA + (r0 + rb * 16 + g) * PB + t * 2;
                a[rb][0] = *(const unsigned*)(base);
                a[rb][1] = *(const unsigned*)(base + 8 * PB);
                a[rb][2] = *(const unsigned*)(base + 8);
                a[rb][3] = *(const unsigned*)(base + 8 * PB + 8);
            }

            // 16-bit fragment mask: bit (cb*2+rb) set if any of this thread's
            // 4 outputs in that 16x8 fragment is < 1.5
            unsigned fmask = 0u;
            #pragma unroll
            for (int cb = 0; cb < 8; ++cb) {
                const __nv_bfloat16* bb = sB + (c0 + cb * 8 + g) * PB + t * 2;
                unsigned b0 = *(const unsigned*)(bb);
                unsigned b1 = *(const unsigned*)(bb + 8);
                #pragma unroll
                for (int rb = 0; rb < 2; ++rb) {
                    float d0, d1, d2, d3;
                    asm("mma.sync.aligned.m16n8k16.row.col.f32.bf16.bf16.f32 "
                        "{%0,%1,%2,%3},{%4,%5,%6,%7},{%8,%9},{%10,%10,%10,%10};"
                        : "=f"(d0), "=f"(d1), "=f"(d2), "=f"(d3)
                        : "r"(a[rb][0]), "r"(a[rb][1]), "r"(a[rb][2]), "r"(a[rb][3]),
                          "r"(b0), "r"(b1), "f"(0.0f));
                    float mn = fminf(fminf(d0, d1), fminf(d2, d3));
                    if (mn < 1.5f) fmask |= 1u << (cb * 2 + rb);
                }
            }

            if (fmask) {   // ~8 pairs chip-wide survive the 14-dim screen
                #pragma unroll 1
                while (fmask) {
                    int b = __ffs(fmask) - 1;
                    fmask &= fmask - 1;
                    int cb = b >> 1, rb = b & 1;
                    int gib = row0 + r0 + rb * 16 + g;
                    int gjb = col0 + c0 + cb * 8 + t * 2;
                    #pragma unroll 1
                    for (int q = 0; q < 4; ++q) {
                        int gi = gib + (q >> 1) * 8;
                        int gj = gjb + (q & 1);
                        if (gi < n0 && gj < n1) lsum += rare_pair(gi, gj);
                    }
                }
            }
        }
    }

    // ---- one reduction per block ----
    lsum = warp_sum(lsum);
    if ((tid & 31) == 0) redw[tid >> 5] = lsum;
    __syncthreads();
    if (tid == 0) {
        float s = 0.0f;
        #pragma unroll
        for (int w = 0; w < 8; ++w) s += redw[w];
        if (s != 0.0f) atomicAdd(&d_cross, (double)s);
    }

    // ---- completion ticket: last block finalizes + resets ----
    __threadfence();
    if (tid == 0) s_ticket = atomicAdd(&d_done, 1u);
    __syncthreads();
    if (s_ticket == CROSS_BLOCKS - 1) {
        __threadfence();
        __shared__ double s[256];
        int cls = tid >> 7, comp = tid & 127;
        double v = (double)d_vsum[cls][comp];
        s[tid] = v * v;
        __syncthreads();
        for (int st = 64; st > 0; st >>= 1) {
            if (comp < st) s[tid] += s[tid + st];
            __syncthreads();
        }
        if (tid == 0) {
            double vn0 = s[0], vn1 = s[128];
            double dn0 = (double)n0, dn1 = (double)n1;
            double same = 2.0 * (dn0 * d_acc[2] - vn0) + 2.0 * (dn1 * d_acc[3] - vn1);
            double NN = (double)N_ROWS * (double)N_ROWS;
            double contrast = (same + 2.0 * d_cross) / NN;
            double focal = d_acc[0] / (double)N_ROWS;
            double graph = 0.1 * d_acc[1] / (double)(N_ROWS - 1);
            out[0] = (float)(focal + contrast + graph);
            d_cnt64 = 0ull;
            d_acc[0] = 0.0; d_acc[1] = 0.0; d_acc[2] = 0.0; d_acc[3] = 0.0;
            d_cross = 0.0;
            d_done = 0u;
        }
        d_vsum[cls][comp] = 0.0f;
    }
}

// ---------------- launch ----------------
extern "C" void kernel_launch(void* const* d_in, const int* in_sizes, int n_in,
                              void* d_out, int out_size) {
    const float* preds    = (const float*)d_in[0];
    const float* targets  = (const float*)d_in[1];
    const float* features = (const float*)d_in[2];
    const float* gfeat    = (const float*)d_in[3];
    float* out = (float*)d_out;

    partition_kernel<<<N_ROWS / 8, 256>>>(preds, targets, features, gfeat);
    cross_kernel<<<dim3(CGX, CGY), 256>>>(out);
}

// round 10
// speedup vs baseline: 32.6238x; 1.0374x over previous
#include <cuda_runtime.h>
#include <cuda_bf16.h>
#include <math.h>

#define N_ROWS 8192
#define D_DIM  128
#define CROSS_BLOCKS 1056   // >= max over splits of ceil(n0/128)*ceil(n1/128)
#define PB 24               // smem pitch in bf16 (48B): conflict-free frag loads

// ---------------- device scratch ----------------
__device__ float         d_F[2][N_ROWS * D_DIM];   // compacted features (recheck)
__device__ __nv_bfloat16 d_Ebf[2][N_ROWS * 16];    // bf16 screen rows: 14 dims + 2 aux
__device__ float         d_rsq[2][N_ROWS];
__device__ unsigned long long d_cnt64;             // packed counts: lo=class0, hi=class1
__device__ float         d_vsum[2][D_DIM];
__device__ double        d_acc[4];                 // focal, graph, Snorm0, Snorm1
__device__ double        d_cross;
__device__ unsigned      d_done;

__device__ __forceinline__ float warp_sum(float v) {
    #pragma unroll
    for (int o = 16; o > 0; o >>= 1) v += __shfl_xor_sync(0xffffffffu, v, o);
    return v;
}

// ---------------- partition + focal + graph + class stats ----------------
__global__ void __launch_bounds__(256) partition_kernel(
    const float* __restrict__ preds,
    const float* __restrict__ targets,
    const float* __restrict__ features,
    const float* __restrict__ gfeat)
{
    __shared__ float s_v[8][D_DIM];
    __shared__ float s_sn[2];
    __shared__ float s_focal, s_graph;
    __shared__ int   s_lab[8];
    __shared__ int   s_base[2];

    int tid = threadIdx.x;
    if (tid == 254) { s_sn[0] = 0.0f; s_sn[1] = 0.0f; }
    if (tid == 255) { s_focal = 0.0f; s_graph = 0.0f; }

    int warp = tid >> 5, lane = tid & 31;
    int i = blockIdx.x * 8 + warp;

    float4 f = *(const float4*)(features + (size_t)i * D_DIM + lane * 4);
    float c  = f.x*f.x + f.y*f.y + f.z*f.z + f.w*f.w;
    float nsq   = warp_sum(c);
    float c14 = (lane < 3) ? c : ((lane == 3) ? (f.x*f.x + f.y*f.y) : 0.0f);
    float nsq14 = warp_sum(c14);

    float tgt = targets[i];
    int lab = (tgt > 0.5f) ? 1 : 0;
    if (lane == 0) s_lab[warp] = lab;

    s_v[warp][lane * 4 + 0] = f.x;
    s_v[warp][lane * 4 + 1] = f.y;
    s_v[warp][lane * 4 + 2] = f.z;
    s_v[warp][lane * 4 + 3] = f.w;
    __syncthreads();

    if (tid == 0) {
        int c1 = 0;
        #pragma unroll
        for (int w = 0; w < 8; ++w) c1 += s_lab[w];
        unsigned long long add = ((unsigned long long)c1 << 32)
                               | (unsigned long long)(8 - c1);
        unsigned long long old = atomicAdd(&d_cnt64, add);
        s_base[0] = (int)(old & 0xffffffffull);
        s_base[1] = (int)(old >> 32);
    }
    __syncthreads();

    int rank = 0;
    #pragma unroll
    for (int w = 0; w < 8; ++w) rank += (w < warp && s_lab[w] == lab);
    int idx = s_base[lab] + rank;

    *(float4*)(d_F[lab] + (size_t)idx * D_DIM + lane * 4) = f;
    if (lane == 0) d_rsq[lab][idx] = nsq;

    {   // bf16 screen row: dims0-13 = +/-sqrt2*x, dims14-15 aux
        float s = (lab == 0) ? -1.41421356237f : 1.41421356237f;
        __nv_bfloat16* E = d_Ebf[lab] + (size_t)idx * 16;
        if (lane < 3) {
            __nv_bfloat162 p0 = __floats2bfloat162_rn(s*f.x, s*f.y);
            __nv_bfloat162 p1 = __floats2bfloat162_rn(s*f.z, s*f.w);
            *(__nv_bfloat162*)(E + lane * 4)     = p0;
            *(__nv_bfloat162*)(E + lane * 4 + 2) = p1;
        } else if (lane == 3) {
            __nv_bfloat162 p0 = __floats2bfloat162_rn(s*f.x, s*f.y);  // dims 12,13
            __nv_bfloat16 nb  = __float2bfloat16(nsq14);
            __nv_bfloat16 one = __float2bfloat16(1.0f);
            __nv_bfloat162 aux = (lab == 0) ? __halves2bfloat162(nb, one)
                                            : __halves2bfloat162(one, nb);
            *(__nv_bfloat162*)(E + 12) = p0;
            *(__nv_bfloat162*)(E + 14) = aux;
        }
    }

    if (lane == 0) atomicAdd(&s_sn[lab], nsq);
    if (lane == 0) {
        float p = preds[i];
        float bce = fmaxf(p, 0.0f) - p * tgt + log1pf(expf(-fabsf(p)));
        float pt = expf(-bce);
        float om = 1.0f - pt;
        atomicAdd(&s_focal, 0.25f * om * om * bce);
    }

    if (i >= 1) {
        const float4 a = *(const float4*)(gfeat + (size_t)i       * D_DIM + lane * 4);
        const float4 b = *(const float4*)(gfeat + (size_t)(i - 1) * D_DIM + lane * 4);
        float dx = a.x - b.x, dy = a.y - b.y, dz = a.z - b.z, dw = a.w - b.w;
        float ds = warp_sum(dx*dx + dy*dy + dz*dz + dw*dw);
        if (lane == 0) atomicAdd(&s_graph, sqrtf(ds));
    }
    __syncthreads();

    {
        int cls = tid >> 7, comp = tid & 127;
        float sum = 0.0f;
        #pragma unroll
        for (int w = 0; w < 8; ++w)
            if (s_lab[w] == cls) sum += s_v[w][comp];
        if (sum != 0.0f) atomicAdd(&d_vsum[cls][comp], sum);
    }
    if (tid == 0) {
        atomicAdd(&d_acc[0], (double)s_focal);
        atomicAdd(&d_acc[1], (double)s_graph);
        atomicAdd(&d_acc[2], (double)s_sn[0]);
        atomicAdd(&d_acc[3], (double)s_sn[1]);
    }
}

// exact fp32 recheck; out-of-line, never touches mma regs
__device__ __noinline__ float rare_pair(int gi, int gj) {
    const float* A = d_F[0] + (size_t)gi * D_DIM;
    const float* B = d_F[1] + (size_t)gj * D_DIM;
    float dot = 0.0f;
    #pragma unroll 4
    for (int d = 0; d < D_DIM; ++d) dot += A[d] * B[d];
    float sq = fmaxf(d_rsq[0][gi] + d_rsq[1][gj] - 2.0f * dot, 0.0f);
    float t = 1.0f - sqrtf(sq);
    return (t > 0.0f) ? t * t : 0.0f;
}

// ---------------- cross-label screen via bf16 HMMA (acc == sq14) ------------
// one 128x128 tile-pair per block; flat grid, runtime rectangle mapping
__global__ void __launch_bounds__(256, 4) cross_kernel(float* __restrict__ out) {
    __shared__ __nv_bfloat16 sA[128 * PB];
    __shared__ __nv_bfloat16 sB[128 * PB];
    __shared__ float redw[8];
    __shared__ unsigned s_ticket;

    unsigned long long cnt = d_cnt64;
    int n0 = (int)(cnt & 0xffffffffull);
    int n1 = (int)(cnt >> 32);
    int tiles_r = (n0 + 127) >> 7;
    int tiles_c = (n1 + 127) >> 7;
    int tid = threadIdx.x;
    int bid = blockIdx.x;

    float lsum = 0.0f;

    if (tiles_c > 0 && bid < tiles_r * tiles_c) {
        int tr = bid / tiles_c;
        int tc = bid - tr * tiles_c;
        int row0 = tr * 128, col0 = tc * 128;

        int wid = tid >> 5, lane = tid & 31;
        int g = lane >> 2, t = lane & 3;
        int r0 = (wid & 3) * 32;
        int c0 = (wid >> 2) * 64;

        int ldr = tid >> 1, ldh = tid & 1;
        const uint4 pad = make_uint4(0u, 0u, 0u, 0u);
        const uint4 padaux = make_uint4(0u, 0u, 0u, 0x71157115u);

        // ---- both tile LDGs issued back-to-back (MLP=2), one sync ----
        uint4 va = ldh ? padaux : pad;
        if (row0 + ldr < n0)
            va = *((const uint4*)(d_Ebf[0] + (size_t)(row0 + ldr) * 16) + ldh);
        uint4 vb = ldh ? padaux : pad;
        if (col0 + ldr < n1)
            vb = *((const uint4*)(d_Ebf[1] + (size_t)(col0 + ldr) * 16) + ldh);
        *(uint4*)(sA + ldr * PB + ldh * 8) = va;
        *(uint4*)(sB + ldr * PB + ldh * 8) = vb;
        __syncthreads();

        // ---- A fragments ----
        unsigned a[2][4];
        #pragma unroll
        for (int rb = 0; rb < 2; ++rb) {
            const __nv_bfloat16* base = sA + (r0 + rb * 16 + g) * PB + t * 2;
            a[rb][0] = *(const unsigned*)(base);
            a[rb][1] = *(const unsigned*)(base + 8 * PB);
            a[rb][2] = *(const unsigned*)(base + 8);
            a[rb][3] = *(const unsigned*)(base + 8 * PB + 8);
        }

        unsigned fmask = 0u;
        #pragma unroll
        for (int cb = 0; cb < 8; ++cb) {
            const __nv_bfloat16* bb = sB + (c0 + cb * 8 + g) * PB + t * 2;
            unsigned b0 = *(const unsigned*)(bb);
            unsigned b1 = *(const unsigned*)(bb + 8);
            #pragma unroll
            for (int rb = 0; rb < 2; ++rb) {
                float d0, d1, d2, d3;
                asm("mma.sync.aligned.m16n8k16.row.col.f32.bf16.bf16.f32 "
                    "{%0,%1,%2,%3},{%4,%5,%6,%7},{%8,%9},{%10,%10,%10,%10};"
                    : "=f"(d0), "=f"(d1), "=f"(d2), "=f"(d3)
                    : "r"(a[rb][0]), "r"(a[rb][1]), "r"(a[rb][2]), "r"(a[rb][3]),
                      "r"(b0), "r"(b1), "f"(0.0f));
                float mn = fminf(fminf(d0, d1), fminf(d2, d3));
                if (mn < 1.5f) fmask |= 1u << (cb * 2 + rb);
            }
        }

        if (fmask) {   // ~a handful of pairs chip-wide survive the 14-dim screen
            #pragma unroll 1
            while (fmask) {
                int b = __ffs(fmask) - 1;
                fmask &= fmask - 1;
                int cb = b >> 1, rb = b & 1;
                int gib = row0 + r0 + rb * 16 + g;
                int gjb = col0 + c0 + cb * 8 + t * 2;
                #pragma unroll 1
                for (int q = 0; q < 4; ++q) {
                    int gi = gib + (q >> 1) * 8;
                    int gj = gjb + (q & 1);
                    if (gi < n0 && gj < n1) lsum += rare_pair(gi, gj);
                }
            }
        }
    }

    // ---- one reduction per block ----
    lsum = warp_sum(lsum);
    if ((tid & 31) == 0) redw[tid >> 5] = lsum;
    __syncthreads();
    if (tid == 0) {
        float s = 0.0f;
        #pragma unroll
        for (int w = 0; w < 8; ++w) s += redw[w];
        if (s != 0.0f) atomicAdd(&d_cross, (double)s);
    }

    // ---- completion ticket: last block finalizes + resets ----
    __threadfence();
    if (tid == 0) s_ticket = atomicAdd(&d_done, 1u);
    __syncthreads();
    if (s_ticket == CROSS_BLOCKS - 1) {
        __threadfence();
        __shared__ double s[256];
        int cls = tid >> 7, comp = tid & 127;
        double v = (double)d_vsum[cls][comp];
        s[tid] = v * v;
        __syncthreads();
        for (int st = 64; st > 0; st >>= 1) {
            if (comp < st) s[tid] += s[tid + st];
            __syncthreads();
        }
        if (tid == 0) {
            double vn0 = s[0], vn1 = s[128];
            double dn0 = (double)n0, dn1 = (double)n1;
            double same = 2.0 * (dn0 * d_acc[2] - vn0) + 2.0 * (dn1 * d_acc[3] - vn1);
            double NN = (double)N_ROWS * (double)N_ROWS;
            double contrast = (same + 2.0 * d_cross) / NN;
            double focal = d_acc[0] / (double)N_ROWS;
            double graph = 0.1 * d_acc[1] / (double)(N_ROWS - 1);
            out[0] = (float)(focal + contrast + graph);
            d_cnt64 = 0ull;
            d_acc[0] = 0.0; d_acc[1] = 0.0; d_acc[2] = 0.0; d_acc[3] = 0.0;
            d_cross = 0.0;
            d_done = 0u;
        }
        d_vsum[cls][comp] = 0.0f;
    }
}

// ---------------- launch ----------------
extern "C" void kernel_launch(void* const* d_in, const int* in_sizes, int n_in,
                              void* d_out, int out_size) {
    const float* preds    = (const float*)d_in[0];
    const float* targets  = (const float*)d_in[1];
    const float* features = (const float*)d_in[2];
    const float* gfeat    = (const float*)d_in[3];
    float* out = (float*)d_out;

    partition_kernel<<<N_ROWS / 8, 256>>>(preds, targets, features, gfeat);
    cross_kernel<<<CROSS_BLOCKS, 256>>>(out);
}